// round 4
// baseline (speedup 1.0000x reference)
#include <cuda_runtime.h>
#include <math.h>

#define N_SRC  80000
#define N_TGT  20000
#define E_NUM  80000
#define IN_DIM 128
#define DIM    64
#define EH     128
#define G3     192
#define NK     129   // up to 128 breakpoints -> 129 intervals

// ---------------- scratch (device globals; no allocation) ----------------
__device__ float g_h0[N_SRC * DIM];          // 20.5 MB
__device__ float g_agg[N_TGT * DIM];         // 5.1 MB
__device__ float g_cnt[N_TGT];
__device__ float g_gi[N_TGT * G3];           // 15.4 MB
__device__ float g_M[NK][DIM * DIM];         // 2.1 MB
__device__ float g_P[NK][DIM * DIM];         // 2.1 MB
__device__ float g_thr[EH];
__device__ unsigned char g_act[NK][EH];
__device__ int   g_kedge[E_NUM];
__device__ float g_aedge[E_NUM];
__device__ int   g_used[NK];
__device__ float g_W0t[IN_DIM * DIM];
__device__ float g_Wih_t[DIM * G3];
__device__ float g_Whh_t[DIM * G3];
__device__ float g_W1t[DIM * DIM];
__device__ float g_W2t[DIM * DIM];

__device__ __forceinline__ float sigm(float x) { return 1.0f / (1.0f + expf(-x)); }

// ---------------- zero scratch (must run every launch; graph replays) ----
__global__ void k_zero() {
    int idx = blockIdx.x * blockDim.x + threadIdx.x;
    if (idx < N_TGT * DIM) g_agg[idx] = 0.0f;
    if (idx < N_TGT)       g_cnt[idx] = 0.0f;
    if (idx < NK)          g_used[idx] = 0;
}

// ---------------- transpose small weights for coalesced access ----------
__global__ void k_prep(const float* __restrict__ W0, const float* __restrict__ Wih,
                       const float* __restrict__ Whh, const float* __restrict__ W1,
                       const float* __restrict__ W2) {
    int idx = blockIdx.x * blockDim.x + threadIdx.x;
    if (idx < IN_DIM * DIM) {            // W0t[i*64+o] = W0[o*128+i]
        int i = idx / DIM, o = idx % DIM;
        g_W0t[idx] = W0[o * IN_DIM + i];
    }
    if (idx < DIM * G3) {                // Wih_t[o*192+g] = Wih[g*64+o]
        int o = idx / G3, g = idx % G3;
        g_Wih_t[idx] = Wih[g * DIM + o];
        g_Whh_t[idx] = Whh[g * DIM + o];
    }
    if (idx < DIM * DIM) {               // W1t[i*64+o] = W1[o*64+i]
        int i = idx / DIM, o = idx % DIM;
        g_W1t[idx] = W1[o * DIM + i];
        g_W2t[idx] = W2[o * DIM + i];
    }
}

// ---------------- h0 = relu(x @ W0^T + b0) ------------------------------
// block = 256 threads = 64 outputs x 4 quad-groups; 8 rows per thread.
__global__ __launch_bounds__(256) void k_h0(const float* __restrict__ x,
                                            const float* __restrict__ b0) {
    int o = threadIdx.x & 63;
    int q = threadIdx.x >> 6;           // 0..3
    int row0 = blockIdx.x * 32 + q * 8; // 8 rows per thread
    float acc[8];
#pragma unroll
    for (int r = 0; r < 8; r++) acc[r] = 0.0f;
#pragma unroll 4
    for (int ii = 0; ii < IN_DIM / 4; ii++) {
        float w0 = g_W0t[(ii * 4 + 0) * DIM + o];
        float w1 = g_W0t[(ii * 4 + 1) * DIM + o];
        float w2 = g_W0t[(ii * 4 + 2) * DIM + o];
        float w3 = g_W0t[(ii * 4 + 3) * DIM + o];
#pragma unroll
        for (int r = 0; r < 8; r++) {
            float4 xv = *reinterpret_cast<const float4*>(x + (size_t)(row0 + r) * IN_DIM + ii * 4);
            acc[r] += xv.x * w0 + xv.y * w1 + xv.z * w2 + xv.w * w3;
        }
    }
    float b = b0[o];
#pragma unroll
    for (int r = 0; r < 8; r++)
        g_h0[(size_t)(row0 + r) * DIM + o] = fmaxf(acc[r] + b, 0.0f);
}

// ---------------- sort breakpoints, build active masks -------------------
// 1 block, 128 threads. Exact: relu(s*a+c) active set is constant on each
// open interval between sorted thresholds; boundary terms are exactly 0.
__global__ void k_setup(const float* __restrict__ A1, const float* __restrict__ c1) {
    __shared__ float ts[EH], sorted[EH];
    int j = threadIdx.x;
    float s = A1[j];
    float c = c1[j];
    float t = (s != 0.0f) ? (-c / s) : 2.0e30f;  // s==0: never flips (sentinel)
    ts[j] = t;
    __syncthreads();
    int rank = 0;
    for (int k = 0; k < EH; k++) {
        float tk = ts[k];
        rank += (tk < t) || (tk == t && k < j);
    }
    sorted[rank] = t;
    __syncthreads();
    g_thr[j] = sorted[j];
    const float BIGT = 1.0e29f;
    for (int k = 0; k < NK; k++) {
        float left  = (k > 0)  ? sorted[k - 1] : -2.0e30f;
        float right = (k < EH) ? sorted[k]     :  2.0e30f;
        bool linf = (left <= -BIGT), rinf = (right >= BIGT);
        float rep;
        if (linf && rinf)      rep = 0.0f;
        else if (linf)         rep = right - 1.0f;
        else if (rinf)         rep = left + 1.0f;
        else                   rep = 0.5f * (left + right);
        g_act[k][j] = (s * rep + c > 0.0f) ? 1 : 0;
    }
}

// ---------------- per-edge scalar + interval id --------------------------
__global__ void k_edgek(const int* __restrict__ eids, const float* __restrict__ ew) {
    __shared__ float thr[EH];
    if (threadIdx.x < EH) thr[threadIdx.x] = g_thr[threadIdx.x];
    __syncthreads();
    int e = blockIdx.x * blockDim.x + threadIdx.x;
    if (e >= E_NUM) return;
    float a = ew[eids[e]];
    int k = 0;
#pragma unroll
    for (int j = 0; j < EH; j++) k += (thr[j] < a) ? 1 : 0;
    g_kedge[e] = k;
    g_aedge[e] = a;
    g_used[k]  = 1;
}

// ---------------- build M_k / P_k only for used intervals ----------------
// grid (512, NK), block 256 (8 warps -> 8 io entries per block)
__global__ void k_tables(const float* __restrict__ A1, const float* __restrict__ c1,
                         const float* __restrict__ A2, const float* __restrict__ c2) {
    int k = blockIdx.y;
    if (!g_used[k]) return;
    __shared__ float hs[EH], h2s[EH];
    int t = threadIdx.x;
    if (t < EH) {
        float a = g_act[k][t] ? 1.0f : 0.0f;
        hs[t]  = A1[t] * a;
        h2s[t] = c1[t] * a;
    }
    __syncthreads();
    int w = t >> 5, l = t & 31;
    int io = blockIdx.x * 8 + w;
    const float4 av = *reinterpret_cast<const float4*>(A2 + (size_t)io * EH + l * 4);
    float m = av.x * hs[l * 4] + av.y * hs[l * 4 + 1] + av.z * hs[l * 4 + 2] + av.w * hs[l * 4 + 3];
    float p = av.x * h2s[l * 4] + av.y * h2s[l * 4 + 1] + av.z * h2s[l * 4 + 2] + av.w * h2s[l * 4 + 3];
#pragma unroll
    for (int off = 16; off > 0; off >>= 1) {
        m += __shfl_down_sync(0xffffffffu, m, off);
        p += __shfl_down_sync(0xffffffffu, p, off);
    }
    if (l == 0) {
        g_M[k][io] = m;
        g_P[k][io] = c2[io] + p;
    }
}

// ---------------- edge messages + segment sum ----------------------------
// warp per edge: msg = a*(xs@M_k) + xs@P_k, atomic add into agg[dst]
__global__ __launch_bounds__(256) void k_edges(const int* __restrict__ esrc,
                                               const int* __restrict__ edst) {
    int e = (blockIdx.x * blockDim.x + threadIdx.x) >> 5;
    int l = threadIdx.x & 31;
    if (e >= E_NUM) return;
    int src = esrc[e], dst = edst[e];
    float a = g_aedge[e];
    int   k = g_kedge[e];
    const float* __restrict__ M = g_M[k];
    const float* __restrict__ P = g_P[k];
    float xs0 = g_h0[(size_t)src * DIM + l];
    float xs1 = g_h0[(size_t)src * DIM + 32 + l];
    float acc0 = 0.0f, acc1 = 0.0f;
#pragma unroll 8
    for (int i = 0; i < DIM; i++) {
        float xi  = __shfl_sync(0xffffffffu, (i < 32) ? xs0 : xs1, i & 31);
        float axi = a * xi;
        float m0 = M[i * DIM + l],      m1 = M[i * DIM + 32 + l];
        float p0 = P[i * DIM + l],      p1 = P[i * DIM + 32 + l];
        acc0 += axi * m0 + xi * p0;
        acc1 += axi * m1 + xi * p1;
    }
    atomicAdd(&g_agg[(size_t)dst * DIM + l],      acc0);
    atomicAdd(&g_agg[(size_t)dst * DIM + 32 + l], acc1);
    if (l == 0) atomicAdd(&g_cnt[dst], 1.0f);
}

// ---------------- m = relu(agg/cnt + x_tgt@W_root + b_conv); gi = m@Wih^T + b_ih
// warp handles 4 rows (amortize weight loads)
__global__ __launch_bounds__(256) void k_mgi(const float* __restrict__ W_root,
                                             const float* __restrict__ b_conv,
                                             const float* __restrict__ b_ih) {
    int gw = (blockIdx.x * blockDim.x + threadIdx.x) >> 5;
    int l = threadIdx.x & 31;
    int r0 = gw * 4;
    if (r0 >= N_TGT) return;
    float xt0[4], xt1[4], m0[4], m1[4];
#pragma unroll
    for (int q = 0; q < 4; q++) {
        int row = r0 + q;
        xt0[q] = g_h0[(size_t)row * DIM + l];
        xt1[q] = g_h0[(size_t)row * DIM + 32 + l];
        float inv = 1.0f / fmaxf(g_cnt[row], 1.0f);
        m0[q] = g_agg[(size_t)row * DIM + l] * inv;
        m1[q] = g_agg[(size_t)row * DIM + 32 + l] * inv;
    }
#pragma unroll 4
    for (int i = 0; i < DIM; i++) {
        float w0 = W_root[i * DIM + l];
        float w1 = W_root[i * DIM + 32 + l];
#pragma unroll
        for (int q = 0; q < 4; q++) {
            float xi = __shfl_sync(0xffffffffu, (i < 32) ? xt0[q] : xt1[q], i & 31);
            m0[q] += xi * w0;
            m1[q] += xi * w1;
        }
    }
    float bc0 = b_conv[l], bc1 = b_conv[32 + l];
#pragma unroll
    for (int q = 0; q < 4; q++) {
        m0[q] = fmaxf(m0[q] + bc0, 0.0f);
        m1[q] = fmaxf(m1[q] + bc1, 0.0f);
    }
    float gi[6][4];
#pragma unroll
    for (int t = 0; t < 6; t++)
#pragma unroll
        for (int q = 0; q < 4; q++) gi[t][q] = 0.0f;
#pragma unroll 2
    for (int o = 0; o < DIM; o++) {
        float w[6];
#pragma unroll
        for (int t = 0; t < 6; t++) w[t] = g_Wih_t[o * G3 + l + 32 * t];
#pragma unroll
        for (int q = 0; q < 4; q++) {
            float mo = __shfl_sync(0xffffffffu, (o < 32) ? m0[q] : m1[q], o & 31);
#pragma unroll
            for (int t = 0; t < 6; t++) gi[t][q] += mo * w[t];
        }
    }
#pragma unroll
    for (int t = 0; t < 6; t++) {
        float bi = b_ih[l + 32 * t];
#pragma unroll
        for (int q = 0; q < 4; q++)
            g_gi[(size_t)(r0 + q) * G3 + l + 32 * t] = gi[t][q] + bi;
    }
}

// ---------------- GRU x3 + output head (fully per-row) -------------------
__global__ __launch_bounds__(256) void k_gru(const float* __restrict__ b_hh,
                                             const float* __restrict__ b1,
                                             const float* __restrict__ b2,
                                             float* __restrict__ out) {
    int gw = (blockIdx.x * blockDim.x + threadIdx.x) >> 5;
    int l = threadIdx.x & 31;
    int r0 = gw * 4;
    if (r0 >= N_TGT) return;
    float h0r[4], h1r[4], gi[6][4];
#pragma unroll
    for (int q = 0; q < 4; q++) {
        h0r[q] = g_h0[(size_t)(r0 + q) * DIM + l];
        h1r[q] = g_h0[(size_t)(r0 + q) * DIM + 32 + l];
#pragma unroll
        for (int t = 0; t < 6; t++)
            gi[t][q] = g_gi[(size_t)(r0 + q) * G3 + l + 32 * t];
    }
    float bh[6];
#pragma unroll
    for (int t = 0; t < 6; t++) bh[t] = b_hh[l + 32 * t];

    for (int step = 0; step < 3; step++) {
        float gh[6][4];
#pragma unroll
        for (int t = 0; t < 6; t++)
#pragma unroll
            for (int q = 0; q < 4; q++) gh[t][q] = bh[t];
#pragma unroll 2
        for (int i = 0; i < DIM; i++) {
            float w[6];
#pragma unroll
            for (int t = 0; t < 6; t++) w[t] = g_Whh_t[i * G3 + l + 32 * t];
#pragma unroll
            for (int q = 0; q < 4; q++) {
                float hi = __shfl_sync(0xffffffffu, (i < 32) ? h0r[q] : h1r[q], i & 31);
#pragma unroll
                for (int t = 0; t < 6; t++) gh[t][q] += hi * w[t];
            }
        }
#pragma unroll
        for (int q = 0; q < 4; q++) {
            float rr0 = sigm(gi[0][q] + gh[0][q]);
            float rr1 = sigm(gi[1][q] + gh[1][q]);
            float zz0 = sigm(gi[2][q] + gh[2][q]);
            float zz1 = sigm(gi[3][q] + gh[3][q]);
            float nn0 = tanhf(gi[4][q] + rr0 * gh[4][q]);
            float nn1 = tanhf(gi[5][q] + rr1 * gh[5][q]);
            h0r[q] = (1.0f - zz0) * nn0 + zz0 * h0r[q];
            h1r[q] = (1.0f - zz1) * nn1 + zz1 * h1r[q];
        }
    }
    // head: o1 = relu(h @ W1^T + b1); out = o1 @ W2^T + b2
    float a0[4], a1[4];
#pragma unroll
    for (int q = 0; q < 4; q++) { a0[q] = 0.0f; a1[q] = 0.0f; }
#pragma unroll 4
    for (int i = 0; i < DIM; i++) {
        float w0 = g_W1t[i * DIM + l];
        float w1 = g_W1t[i * DIM + 32 + l];
#pragma unroll
        for (int q = 0; q < 4; q++) {
            float hi = __shfl_sync(0xffffffffu, (i < 32) ? h0r[q] : h1r[q], i & 31);
            a0[q] += hi * w0;
            a1[q] += hi * w1;
        }
    }
    float bb0 = b1[l], bb1 = b1[32 + l];
#pragma unroll
    for (int q = 0; q < 4; q++) {
        a0[q] = fmaxf(a0[q] + bb0, 0.0f);
        a1[q] = fmaxf(a1[q] + bb1, 0.0f);
    }
    float c0[4], c1v[4];
#pragma unroll
    for (int q = 0; q < 4; q++) { c0[q] = 0.0f; c1v[q] = 0.0f; }
#pragma unroll 4
    for (int i = 0; i < DIM; i++) {
        float w0 = g_W2t[i * DIM + l];
        float w1 = g_W2t[i * DIM + 32 + l];
#pragma unroll
        for (int q = 0; q < 4; q++) {
            float oi = __shfl_sync(0xffffffffu, (i < 32) ? a0[q] : a1[q], i & 31);
            c0[q] += oi * w0;
            c1v[q] += oi * w1;
        }
    }
    float ob0 = b2[l], ob1 = b2[32 + l];
#pragma unroll
    for (int q = 0; q < 4; q++) {
        out[(size_t)(r0 + q) * DIM + l]      = c0[q] + ob0;
        out[(size_t)(r0 + q) * DIM + 32 + l] = c1v[q] + ob1;
    }
}

// ---------------- launch ---------------------------------------------------
extern "C" void kernel_launch(void* const* d_in, const int* in_sizes, int n_in,
                              void* d_out, int out_size) {
    const float* x        = (const float*)d_in[0];
    // d_in[1] = flat (unused by reference)
    const int*   edge_src = (const int*)d_in[2];
    const int*   edge_dst = (const int*)d_in[3];
    const int*   edge_ids = (const int*)d_in[4];
    const float* edge_w   = (const float*)d_in[5];
    const float* W0       = (const float*)d_in[6];
    const float* b0       = (const float*)d_in[7];
    const float* A1       = (const float*)d_in[8];
    const float* c1       = (const float*)d_in[9];
    const float* A2       = (const float*)d_in[10];
    const float* c2       = (const float*)d_in[11];
    const float* W_root   = (const float*)d_in[12];
    const float* b_conv   = (const float*)d_in[13];
    const float* W_ih     = (const float*)d_in[14];
    const float* W_hh     = (const float*)d_in[15];
    const float* b_ih     = (const float*)d_in[16];
    const float* b_hh     = (const float*)d_in[17];
    const float* W1       = (const float*)d_in[18];
    const float* b1       = (const float*)d_in[19];
    const float* W2       = (const float*)d_in[20];
    const float* b2       = (const float*)d_in[21];
    float* out = (float*)d_out;

    k_zero<<<(N_TGT * DIM + 255) / 256, 256>>>();
    k_prep<<<(DIM * G3 + 255) / 256, 256>>>(W0, W_ih, W_hh, W1, W2);
    k_setup<<<1, 128>>>(A1, c1);
    k_edgek<<<(E_NUM + 255) / 256, 256>>>(edge_ids, edge_w);
    {
        dim3 g(512, NK, 1);
        k_tables<<<g, 256>>>(A1, c1, A2, c2);
    }
    k_h0<<<N_SRC / 32, 256>>>(x, b0);
    k_edges<<<(E_NUM * 32) / 256, 256>>>(edge_src, edge_dst);
    k_mgi<<<(N_TGT / 4 * 32) / 256, 256>>>(W_root, b_conv, b_ih);
    k_gru<<<(N_TGT / 4 * 32) / 256, 256>>>(b_hh, b1, b2, out);
}

// round 5
// speedup vs baseline: 1.4099x; 1.4099x over previous
#include <cuda_runtime.h>
#include <math.h>

#define N_SRC  80000
#define N_TGT  20000
#define E_NUM  80000
#define IN_DIM 128
#define DIM    64
#define EH     128
#define G3     192
#define NK     129   // up to 128 breakpoints -> 129 intervals
#define MAXU   2     // intervals cached in fast path (fallback covers the rest)

typedef unsigned long long ull;

// ---------------- f32x2 helpers ------------------------------------------
__device__ __forceinline__ ull pk2(float lo, float hi) {
    ull r; asm("mov.b64 %0, {%1,%2};" : "=l"(r) : "f"(lo), "f"(hi)); return r;
}
__device__ __forceinline__ void upk(ull v, float& lo, float& hi) {
    asm("mov.b64 {%0,%1}, %2;" : "=f"(lo), "=f"(hi) : "l"(v));
}
#define FMA_X2(d, a, b, c) asm("fma.rn.f32x2 %0, %1, %2, %3;" : "=l"(d) : "l"(a), "l"(b), "l"(c))

__device__ __forceinline__ float sigm(float x)  { return __fdividef(1.0f, 1.0f + __expf(-x)); }
__device__ __forceinline__ float tanhx(float x) { return 1.0f - __fdividef(2.0f, 1.0f + __expf(2.0f * x)); }

// ---------------- scratch (device globals; no allocation) ----------------
__device__ float g_h0[N_SRC * DIM];
__device__ float g_agg[N_TGT * DIM];
__device__ float g_cnt[N_TGT];
__device__ float g_gi[N_TGT * G3];
__device__ float g_S0[N_TGT * MAXU * DIM];
__device__ float g_S1[N_TGT * MAXU * DIM];
__device__ float g_M[NK][DIM * DIM];
__device__ float g_P[NK][DIM * DIM];
__device__ float g_thr[EH];
__device__ unsigned char g_act[NK][EH];
__device__ int   g_kedge[E_NUM];
__device__ float g_aedge[E_NUM];
__device__ int   g_used[NK];
__device__ int   g_slotmap[NK];
__device__ int   g_slotk[MAXU];
__device__ int   g_nslots;
__device__ float g_W0t[IN_DIM * DIM];
__device__ ull   g_Wih_d[DIM * G3];
__device__ ull   g_Whh_d[DIM * G3];
__device__ ull   g_Wr_d[DIM * DIM];
__device__ ull   g_W1d[DIM * DIM];
__device__ ull   g_W2d[DIM * DIM];

// ---------------- zero scratch -------------------------------------------
__global__ void k_zero() {
    int idx = blockIdx.x * blockDim.x + threadIdx.x;
    if (idx < N_TGT * MAXU * DIM) { g_S0[idx] = 0.0f; g_S1[idx] = 0.0f; }
    if (idx < N_TGT * DIM) g_agg[idx] = 0.0f;
    if (idx < N_TGT)       g_cnt[idx] = 0.0f;
    if (idx < NK)          g_used[idx] = 0;
}

// ---------------- weight prep: transpose + f32x2-dup tables --------------
__global__ void k_prep(const float* __restrict__ W0, const float* __restrict__ Wih,
                       const float* __restrict__ Whh, const float* __restrict__ Wr,
                       const float* __restrict__ W1, const float* __restrict__ W2) {
    int idx = blockIdx.x * blockDim.x + threadIdx.x;
    if (idx < IN_DIM * DIM) {            // W0t[i*64+o] = W0[o*128+i]
        int i = idx / DIM, o = idx % DIM;
        g_W0t[idx] = W0[o * IN_DIM + i];
    }
    if (idx < DIM * G3) {                // [o][g] dup tables
        int o = idx / G3, g = idx % G3;
        float wi = Wih[g * DIM + o]; g_Wih_d[idx] = pk2(wi, wi);
        float wh = Whh[g * DIM + o]; g_Whh_d[idx] = pk2(wh, wh);
    }
    if (idx < DIM * DIM) {
        int i = idx / DIM, o = idx % DIM;
        float wr = Wr[idx];          g_Wr_d[idx] = pk2(wr, wr);
        float w1 = W1[o * DIM + i];  g_W1d[idx] = pk2(w1, w1);
        float w2 = W2[o * DIM + i];  g_W2d[idx] = pk2(w2, w2);
    }
}

// ---------------- sort breakpoints, build active masks -------------------
__global__ void k_setup(const float* __restrict__ A1, const float* __restrict__ c1) {
    __shared__ float ts[EH], sorted[EH];
    int j = threadIdx.x;
    float s = A1[j];
    float c = c1[j];
    float t = (s != 0.0f) ? (-c / s) : 2.0e30f;
    ts[j] = t;
    __syncthreads();
    int rank = 0;
    for (int k = 0; k < EH; k++) {
        float tk = ts[k];
        rank += (tk < t) || (tk == t && k < j);
    }
    sorted[rank] = t;
    __syncthreads();
    g_thr[j] = sorted[j];
    const float BIGT = 1.0e29f;
    for (int k = 0; k < NK; k++) {
        float left  = (k > 0)  ? sorted[k - 1] : -2.0e30f;
        float right = (k < EH) ? sorted[k]     :  2.0e30f;
        bool linf = (left <= -BIGT), rinf = (right >= BIGT);
        float rep;
        if (linf && rinf)      rep = 0.0f;
        else if (linf)         rep = right - 1.0f;
        else if (rinf)         rep = left + 1.0f;
        else                   rep = 0.5f * (left + right);
        g_act[k][j] = (s * rep + c > 0.0f) ? 1 : 0;
    }
}

// ---------------- per-edge scalar + interval id + dst counts -------------
__global__ void k_edgek(const int* __restrict__ eids, const float* __restrict__ ew,
                        const int* __restrict__ edst) {
    __shared__ float thr[EH];
    if (threadIdx.x < EH) thr[threadIdx.x] = g_thr[threadIdx.x];
    __syncthreads();
    int e = blockIdx.x * blockDim.x + threadIdx.x;
    if (e >= E_NUM) return;
    float a = ew[eids[e]];
    int k = 0;
#pragma unroll
    for (int j = 0; j < EH; j++) k += (thr[j] < a) ? 1 : 0;
    g_kedge[e] = k;
    g_aedge[e] = a;
    g_used[k]  = 1;
    atomicAdd(&g_cnt[edst[e]], 1.0f);
}

// ---------------- deterministic slot assignment (k order) ----------------
__global__ void k_slots() {
    if (threadIdx.x == 0 && blockIdx.x == 0) {
        int ns = 0;
        for (int k = 0; k < NK; k++) {
            if (g_used[k]) {
                g_slotmap[k] = (ns < MAXU) ? ns : -1;
                if (ns < MAXU) g_slotk[ns] = k;
                ns++;
            } else {
                g_slotmap[k] = -1;
            }
        }
        g_nslots = (ns < MAXU) ? ns : MAXU;
    }
}

// ---------------- build M_k / P_k only for used intervals ----------------
__global__ void k_tables(const float* __restrict__ A1, const float* __restrict__ c1,
                         const float* __restrict__ A2, const float* __restrict__ c2) {
    int k = blockIdx.y;
    if (!g_used[k]) return;
    __shared__ float hs[EH], h2s[EH];
    int t = threadIdx.x;
    if (t < EH) {
        float a = g_act[k][t] ? 1.0f : 0.0f;
        hs[t]  = A1[t] * a;
        h2s[t] = c1[t] * a;
    }
    __syncthreads();
    int w = t >> 5, l = t & 31;
    int io = blockIdx.x * 8 + w;
    const float4 av = *reinterpret_cast<const float4*>(A2 + (size_t)io * EH + l * 4);
    float m = av.x * hs[l * 4] + av.y * hs[l * 4 + 1] + av.z * hs[l * 4 + 2] + av.w * hs[l * 4 + 3];
    float p = av.x * h2s[l * 4] + av.y * h2s[l * 4 + 1] + av.z * h2s[l * 4 + 2] + av.w * h2s[l * 4 + 3];
#pragma unroll
    for (int off = 16; off > 0; off >>= 1) {
        m += __shfl_down_sync(0xffffffffu, m, off);
        p += __shfl_down_sync(0xffffffffu, p, off);
    }
    if (l == 0) {
        g_M[k][io] = m;
        g_P[k][io] = c2[io] + p;
    }
}

// ---------------- h0 = relu(x @ W0^T + b0), FFMA2 version ----------------
// thread = output-pair (2j,2j+1) x 4 rows; block covers 32 rows.
__global__ __launch_bounds__(256) void k_h0(const float* __restrict__ x,
                                            const float* __restrict__ b0) {
    int j  = threadIdx.x & 31;          // output pair index
    int gq = threadIdx.x >> 5;          // 0..7
    int row0 = blockIdx.x * 32 + gq * 4;
    ull acc[4] = {0ull, 0ull, 0ull, 0ull};
    const ull* __restrict__ W = reinterpret_cast<const ull*>(g_W0t);
#pragma unroll 4
    for (int ii = 0; ii < IN_DIM / 4; ii++) {
        float4 xv0 = *reinterpret_cast<const float4*>(x + (size_t)(row0 + 0) * IN_DIM + ii * 4);
        float4 xv1 = *reinterpret_cast<const float4*>(x + (size_t)(row0 + 1) * IN_DIM + ii * 4);
        float4 xv2 = *reinterpret_cast<const float4*>(x + (size_t)(row0 + 2) * IN_DIM + ii * 4);
        float4 xv3 = *reinterpret_cast<const float4*>(x + (size_t)(row0 + 3) * IN_DIM + ii * 4);
#define H0_STEP(comp, s)                                               \
        {                                                              \
            ull wv = W[(ii * 4 + s) * 32 + j];                         \
            FMA_X2(acc[0], pk2(xv0.comp, xv0.comp), wv, acc[0]);       \
            FMA_X2(acc[1], pk2(xv1.comp, xv1.comp), wv, acc[1]);       \
            FMA_X2(acc[2], pk2(xv2.comp, xv2.comp), wv, acc[2]);       \
            FMA_X2(acc[3], pk2(xv3.comp, xv3.comp), wv, acc[3]);       \
        }
        H0_STEP(x, 0) H0_STEP(y, 1) H0_STEP(z, 2) H0_STEP(w, 3)
#undef H0_STEP
    }
    float ba = b0[2 * j], bb = b0[2 * j + 1];
#pragma unroll
    for (int r = 0; r < 4; r++) {
        float lo, hi;
        upk(acc[r], lo, hi);
        float2 v;
        v.x = fmaxf(lo + ba, 0.0f);
        v.y = fmaxf(hi + bb, 0.0f);
        *reinterpret_cast<float2*>(g_h0 + (size_t)(row0 + r) * DIM + 2 * j) = v;
    }
}

// ---------------- edge scatter into S0/S1 (fast) or per-edge matvec ------
__global__ __launch_bounds__(256) void k_scatter(const int* __restrict__ esrc,
                                                 const int* __restrict__ edst) {
    int e = (blockIdx.x * blockDim.x + threadIdx.x) >> 5;
    int l = threadIdx.x & 31;
    if (e >= E_NUM) return;
    int src = esrc[e], dst = edst[e];
    float a = g_aedge[e];
    int   k = g_kedge[e];
    int slot = g_slotmap[k];
    float xs0 = g_h0[(size_t)src * DIM + l];
    float xs1 = g_h0[(size_t)src * DIM + 32 + l];
    if (slot >= 0) {
        size_t base = ((size_t)dst * MAXU + slot) * DIM;
        atomicAdd(&g_S0[base + l],      xs0);
        atomicAdd(&g_S0[base + 32 + l], xs1);
        atomicAdd(&g_S1[base + l],      a * xs0);
        atomicAdd(&g_S1[base + 32 + l], a * xs1);
    } else {
        // exact fallback: per-edge matvec into g_agg
        const float* __restrict__ M = g_M[k];
        const float* __restrict__ P = g_P[k];
        float acc0 = 0.0f, acc1 = 0.0f;
#pragma unroll 8
        for (int i = 0; i < DIM; i++) {
            float xi  = __shfl_sync(0xffffffffu, (i < 32) ? xs0 : xs1, i & 31);
            float axi = a * xi;
            acc0 += axi * M[i * DIM + l]      + xi * P[i * DIM + l];
            acc1 += axi * M[i * DIM + 32 + l] + xi * P[i * DIM + 32 + l];
        }
        atomicAdd(&g_agg[(size_t)dst * DIM + l],      acc0);
        atomicAdd(&g_agg[(size_t)dst * DIM + 32 + l], acc1);
    }
}

// ---------------- dense transform: agg += sum_s S1@M_s + S0@P_s ----------
// warp per 4 targets; tables cached in smem one slot at a time (32 KB).
__global__ __launch_bounds__(256) void k_transform() {
    __shared__ float sM[DIM * DIM], sP[DIM * DIM];
    int ns = g_nslots;
    int gw = (blockIdx.x * 256 + threadIdx.x) >> 5;
    int l  = threadIdx.x & 31;
    int r0 = gw * 4;
    bool valid = (r0 < N_TGT);
    ull accA[2], accB[2];
    if (valid) {
        accA[0] = pk2(g_agg[(size_t)(r0 + 0) * DIM + l],      g_agg[(size_t)(r0 + 1) * DIM + l]);
        accA[1] = pk2(g_agg[(size_t)(r0 + 2) * DIM + l],      g_agg[(size_t)(r0 + 3) * DIM + l]);
        accB[0] = pk2(g_agg[(size_t)(r0 + 0) * DIM + 32 + l], g_agg[(size_t)(r0 + 1) * DIM + 32 + l]);
        accB[1] = pk2(g_agg[(size_t)(r0 + 2) * DIM + 32 + l], g_agg[(size_t)(r0 + 3) * DIM + 32 + l]);
    }
    for (int s = 0; s < ns; s++) {
        __syncthreads();
        int k = g_slotk[s];
        for (int idx = threadIdx.x; idx < DIM * DIM; idx += 256) {
            sM[idx] = g_M[k][idx];
            sP[idx] = g_P[k][idx];
        }
        __syncthreads();
        if (!valid) continue;
        float s0a[4], s0b[4], s1a[4], s1b[4];
#pragma unroll
        for (int q = 0; q < 4; q++) {
            size_t base = ((size_t)(r0 + q) * MAXU + s) * DIM;
            s0a[q] = g_S0[base + l];  s0b[q] = g_S0[base + 32 + l];
            s1a[q] = g_S1[base + l];  s1b[q] = g_S1[base + 32 + l];
        }
#pragma unroll 4
        for (int i = 0; i < DIM; i++) {
            float m0 = sM[i * DIM + l], m1 = sM[i * DIM + 32 + l];
            float p0 = sP[i * DIM + l], p1 = sP[i * DIM + 32 + l];
            float s1q[4], s0q[4];
#pragma unroll
            for (int q = 0; q < 4; q++) {
                s1q[q] = __shfl_sync(0xffffffffu, (i < 32) ? s1a[q] : s1b[q], i & 31);
                s0q[q] = __shfl_sync(0xffffffffu, (i < 32) ? s0a[q] : s0b[q], i & 31);
            }
            ull s1p01 = pk2(s1q[0], s1q[1]), s1p23 = pk2(s1q[2], s1q[3]);
            ull s0p01 = pk2(s0q[0], s0q[1]), s0p23 = pk2(s0q[2], s0q[3]);
            ull m0p = pk2(m0, m0), m1p = pk2(m1, m1);
            ull p0p = pk2(p0, p0), p1p = pk2(p1, p1);
            FMA_X2(accA[0], s1p01, m0p, accA[0]); FMA_X2(accA[0], s0p01, p0p, accA[0]);
            FMA_X2(accA[1], s1p23, m0p, accA[1]); FMA_X2(accA[1], s0p23, p0p, accA[1]);
            FMA_X2(accB[0], s1p01, m1p, accB[0]); FMA_X2(accB[0], s0p01, p1p, accB[0]);
            FMA_X2(accB[1], s1p23, m1p, accB[1]); FMA_X2(accB[1], s0p23, p1p, accB[1]);
        }
    }
    if (valid) {
        float v0, v1;
        upk(accA[0], v0, v1);
        g_agg[(size_t)(r0 + 0) * DIM + l] = v0; g_agg[(size_t)(r0 + 1) * DIM + l] = v1;
        upk(accA[1], v0, v1);
        g_agg[(size_t)(r0 + 2) * DIM + l] = v0; g_agg[(size_t)(r0 + 3) * DIM + l] = v1;
        upk(accB[0], v0, v1);
        g_agg[(size_t)(r0 + 0) * DIM + 32 + l] = v0; g_agg[(size_t)(r0 + 1) * DIM + 32 + l] = v1;
        upk(accB[1], v0, v1);
        g_agg[(size_t)(r0 + 2) * DIM + 32 + l] = v0; g_agg[(size_t)(r0 + 3) * DIM + 32 + l] = v1;
    }
}

// ---------------- m = relu(agg/cnt + x_tgt@W_root + b_conv); gi ----------
__global__ __launch_bounds__(256) void k_mgi(const float* __restrict__ b_conv,
                                             const float* __restrict__ b_ih) {
    int gw = (blockIdx.x * 256 + threadIdx.x) >> 5;
    int l = threadIdx.x & 31;
    int r0 = gw * 4;
    if (r0 >= N_TGT) return;
    float xt0[4], xt1[4];
    ull mA[2], mB[2];
    {
        float a0[4], a1[4];
#pragma unroll
        for (int q = 0; q < 4; q++) {
            int row = r0 + q;
            xt0[q] = g_h0[(size_t)row * DIM + l];
            xt1[q] = g_h0[(size_t)row * DIM + 32 + l];
            float inv = __fdividef(1.0f, fmaxf(g_cnt[row], 1.0f));
            a0[q] = g_agg[(size_t)row * DIM + l] * inv;
            a1[q] = g_agg[(size_t)row * DIM + 32 + l] * inv;
        }
        mA[0] = pk2(a0[0], a0[1]); mA[1] = pk2(a0[2], a0[3]);
        mB[0] = pk2(a1[0], a1[1]); mB[1] = pk2(a1[2], a1[3]);
    }
#pragma unroll 4
    for (int i = 0; i < DIM; i++) {
        ull wv0 = g_Wr_d[i * DIM + l];
        ull wv1 = g_Wr_d[i * DIM + 32 + l];
        float xq[4];
#pragma unroll
        for (int q = 0; q < 4; q++)
            xq[q] = __shfl_sync(0xffffffffu, (i < 32) ? xt0[q] : xt1[q], i & 31);
        ull xp01 = pk2(xq[0], xq[1]), xp23 = pk2(xq[2], xq[3]);
        FMA_X2(mA[0], xp01, wv0, mA[0]); FMA_X2(mA[1], xp23, wv0, mA[1]);
        FMA_X2(mB[0], xp01, wv1, mB[0]); FMA_X2(mB[1], xp23, wv1, mB[1]);
    }
    float m0[4], m1[4];
    {
        float bc0 = b_conv[l], bc1 = b_conv[32 + l];
        float v0, v1;
        upk(mA[0], v0, v1); m0[0] = fmaxf(v0 + bc0, 0.0f); m0[1] = fmaxf(v1 + bc0, 0.0f);
        upk(mA[1], v0, v1); m0[2] = fmaxf(v0 + bc0, 0.0f); m0[3] = fmaxf(v1 + bc0, 0.0f);
        upk(mB[0], v0, v1); m1[0] = fmaxf(v0 + bc1, 0.0f); m1[1] = fmaxf(v1 + bc1, 0.0f);
        upk(mB[1], v0, v1); m1[2] = fmaxf(v0 + bc1, 0.0f); m1[3] = fmaxf(v1 + bc1, 0.0f);
    }
    ull gip[6][2];
#pragma unroll
    for (int t = 0; t < 6; t++) { gip[t][0] = 0ull; gip[t][1] = 0ull; }
#pragma unroll 2
    for (int o = 0; o < DIM; o++) {
        float mq[4];
#pragma unroll
        for (int q = 0; q < 4; q++)
            mq[q] = __shfl_sync(0xffffffffu, (o < 32) ? m0[q] : m1[q], o & 31);
        ull mp01 = pk2(mq[0], mq[1]), mp23 = pk2(mq[2], mq[3]);
#pragma unroll
        for (int t = 0; t < 6; t++) {
            ull wv = g_Wih_d[o * G3 + l + 32 * t];
            FMA_X2(gip[t][0], mp01, wv, gip[t][0]);
            FMA_X2(gip[t][1], mp23, wv, gip[t][1]);
        }
    }
#pragma unroll
    for (int t = 0; t < 6; t++) {
        float bi = b_ih[l + 32 * t];
        float v0, v1;
        upk(gip[t][0], v0, v1);
        g_gi[(size_t)(r0 + 0) * G3 + l + 32 * t] = v0 + bi;
        g_gi[(size_t)(r0 + 1) * G3 + l + 32 * t] = v1 + bi;
        upk(gip[t][1], v0, v1);
        g_gi[(size_t)(r0 + 2) * G3 + l + 32 * t] = v0 + bi;
        g_gi[(size_t)(r0 + 3) * G3 + l + 32 * t] = v1 + bi;
    }
}

// ---------------- GRU x3 + output head -----------------------------------
__global__ __launch_bounds__(256) void k_gru(const float* __restrict__ b_hh,
                                             const float* __restrict__ b1,
                                             const float* __restrict__ b2,
                                             float* __restrict__ out) {
    int gw = (blockIdx.x * 256 + threadIdx.x) >> 5;
    int l = threadIdx.x & 31;
    int r0 = gw * 4;
    if (r0 >= N_TGT) return;
    float h0r[4], h1r[4], gi[6][4];
#pragma unroll
    for (int q = 0; q < 4; q++) {
        h0r[q] = g_h0[(size_t)(r0 + q) * DIM + l];
        h1r[q] = g_h0[(size_t)(r0 + q) * DIM + 32 + l];
#pragma unroll
        for (int t = 0; t < 6; t++)
            gi[t][q] = g_gi[(size_t)(r0 + q) * G3 + l + 32 * t];
    }
    float bh[6];
#pragma unroll
    for (int t = 0; t < 6; t++) bh[t] = b_hh[l + 32 * t];

    for (int step = 0; step < 3; step++) {
        ull ghp[6][2];
#pragma unroll
        for (int t = 0; t < 6; t++) {
            ghp[t][0] = pk2(bh[t], bh[t]);
            ghp[t][1] = ghp[t][0];
        }
#pragma unroll 2
        for (int i = 0; i < DIM; i++) {
            float hq[4];
#pragma unroll
            for (int q = 0; q < 4; q++)
                hq[q] = __shfl_sync(0xffffffffu, (i < 32) ? h0r[q] : h1r[q], i & 31);
            ull hp01 = pk2(hq[0], hq[1]), hp23 = pk2(hq[2], hq[3]);
#pragma unroll
            for (int t = 0; t < 6; t++) {
                ull wv = g_Whh_d[i * G3 + l + 32 * t];
                FMA_X2(ghp[t][0], hp01, wv, ghp[t][0]);
                FMA_X2(ghp[t][1], hp23, wv, ghp[t][1]);
            }
        }
#pragma unroll
        for (int q = 0; q < 4; q++) {
            float ghv[6];
#pragma unroll
            for (int t = 0; t < 6; t++) {
                float lo, hi;
                upk(ghp[t][q >> 1], lo, hi);
                ghv[t] = (q & 1) ? hi : lo;
            }
            float rr0 = sigm(gi[0][q] + ghv[0]);
            float rr1 = sigm(gi[1][q] + ghv[1]);
            float zz0 = sigm(gi[2][q] + ghv[2]);
            float zz1 = sigm(gi[3][q] + ghv[3]);
            float nn0 = tanhx(gi[4][q] + rr0 * ghv[4]);
            float nn1 = tanhx(gi[5][q] + rr1 * ghv[5]);
            h0r[q] = (1.0f - zz0) * nn0 + zz0 * h0r[q];
            h1r[q] = (1.0f - zz1) * nn1 + zz1 * h1r[q];
        }
    }
    // head: a = relu(h @ W1^T + b1)
    ull aA01 = 0ull, aA23 = 0ull, aB01 = 0ull, aB23 = 0ull;
#pragma unroll 4
    for (int i = 0; i < DIM; i++) {
        float hq[4];
#pragma unroll
        for (int q = 0; q < 4; q++)
            hq[q] = __shfl_sync(0xffffffffu, (i < 32) ? h0r[q] : h1r[q], i & 31);
        ull hp01 = pk2(hq[0], hq[1]), hp23 = pk2(hq[2], hq[3]);
        ull wv0 = g_W1d[i * DIM + l], wv1 = g_W1d[i * DIM + 32 + l];
        FMA_X2(aA01, hp01, wv0, aA01); FMA_X2(aA23, hp23, wv0, aA23);
        FMA_X2(aB01, hp01, wv1, aB01); FMA_X2(aB23, hp23, wv1, aB23);
    }
    float a0[4], a1[4];
    {
        float bb0 = b1[l], bb1 = b1[32 + l];
        float v0, v1;
        upk(aA01, v0, v1); a0[0] = fmaxf(v0 + bb0, 0.0f); a0[1] = fmaxf(v1 + bb0, 0.0f);
        upk(aA23, v0, v1); a0[2] = fmaxf(v0 + bb0, 0.0f); a0[3] = fmaxf(v1 + bb0, 0.0f);
        upk(aB01, v0, v1); a1[0] = fmaxf(v0 + bb1, 0.0f); a1[1] = fmaxf(v1 + bb1, 0.0f);
        upk(aB23, v0, v1); a1[2] = fmaxf(v0 + bb1, 0.0f); a1[3] = fmaxf(v1 + bb1, 0.0f);
    }
    // out = a @ W2^T + b2
    ull cA01 = 0ull, cA23 = 0ull, cB01 = 0ull, cB23 = 0ull;
#pragma unroll 4
    for (int i = 0; i < DIM; i++) {
        float aq[4];
#pragma unroll
        for (int q = 0; q < 4; q++)
            aq[q] = __shfl_sync(0xffffffffu, (i < 32) ? a0[q] : a1[q], i & 31);
        ull ap01 = pk2(aq[0], aq[1]), ap23 = pk2(aq[2], aq[3]);
        ull wv0 = g_W2d[i * DIM + l], wv1 = g_W2d[i * DIM + 32 + l];
        FMA_X2(cA01, ap01, wv0, cA01); FMA_X2(cA23, ap23, wv0, cA23);
        FMA_X2(cB01, ap01, wv1, cB01); FMA_X2(cB23, ap23, wv1, cB23);
    }
    {
        float ob0 = b2[l], ob1 = b2[32 + l];
        float v0, v1;
        upk(cA01, v0, v1);
        out[(size_t)(r0 + 0) * DIM + l] = v0 + ob0;
        out[(size_t)(r0 + 1) * DIM + l] = v1 + ob0;
        upk(cA23, v0, v1);
        out[(size_t)(r0 + 2) * DIM + l] = v0 + ob0;
        out[(size_t)(r0 + 3) * DIM + l] = v1 + ob0;
        upk(cB01, v0, v1);
        out[(size_t)(r0 + 0) * DIM + 32 + l] = v0 + ob1;
        out[(size_t)(r0 + 1) * DIM + 32 + l] = v1 + ob1;
        upk(cB23, v0, v1);
        out[(size_t)(r0 + 2) * DIM + 32 + l] = v0 + ob1;
        out[(size_t)(r0 + 3) * DIM + 32 + l] = v1 + ob1;
    }
}

// ---------------- launch ---------------------------------------------------
extern "C" void kernel_launch(void* const* d_in, const int* in_sizes, int n_in,
                              void* d_out, int out_size) {
    const float* x        = (const float*)d_in[0];
    const int*   edge_src = (const int*)d_in[2];
    const int*   edge_dst = (const int*)d_in[3];
    const int*   edge_ids = (const int*)d_in[4];
    const float* edge_w   = (const float*)d_in[5];
    const float* W0       = (const float*)d_in[6];
    const float* b0       = (const float*)d_in[7];
    const float* A1       = (const float*)d_in[8];
    const float* c1       = (const float*)d_in[9];
    const float* A2       = (const float*)d_in[10];
    const float* c2       = (const float*)d_in[11];
    const float* W_root   = (const float*)d_in[12];
    const float* b_conv   = (const float*)d_in[13];
    const float* W_ih     = (const float*)d_in[14];
    const float* W_hh     = (const float*)d_in[15];
    const float* b_ih     = (const float*)d_in[16];
    const float* b_hh     = (const float*)d_in[17];
    const float* W1       = (const float*)d_in[18];
    const float* b1       = (const float*)d_in[19];
    const float* W2       = (const float*)d_in[20];
    const float* b2       = (const float*)d_in[21];
    float* out = (float*)d_out;

    k_zero<<<(N_TGT * MAXU * DIM + 255) / 256, 256>>>();
    k_prep<<<(DIM * G3 + 255) / 256, 256>>>(W0, W_ih, W_hh, W_root, W1, W2);
    k_setup<<<1, 128>>>(A1, c1);
    k_edgek<<<(E_NUM + 255) / 256, 256>>>(edge_ids, edge_w, edge_dst);
    k_slots<<<1, 32>>>();
    {
        dim3 g(512, NK, 1);
        k_tables<<<g, 256>>>(A1, c1, A2, c2);
    }
    k_h0<<<N_SRC / 32, 256>>>(x, b0);
    k_scatter<<<(E_NUM * 32) / 256, 256>>>(edge_src, edge_dst);
    k_transform<<<(N_TGT / 4 + 7) / 8, 256>>>();
    k_mgi<<<(N_TGT / 4 * 32) / 256, 256>>>(b_conv, b_ih);
    k_gru<<<(N_TGT / 4 * 32) / 256, 256>>>(b_hh, b1, b2, out);
}